// round 1
// baseline (speedup 1.0000x reference)
#include <cuda_runtime.h>
#include <float.h>

// Problem shape (fixed by the reference)
#define NB 32
#define NT 2048
#define ND 512

// Pass-1 chunking
#define NC1 16
#define ROWS1 (NT / NC1)           // 128 rows per block

// Pass-2 chunking: grid (NB, NC2), 8 warps/block, warp = partial-softmax unit
#define NC2 8
#define NW2 8
#define RPW ((NT / NC2) / NW2)     // 32 rows per warp
#define NPART (NC2 * NW2)          // 64 partials per batch

// Scratch (no cudaMalloc allowed): ~5.3 MB total
__device__ __align__(16) float g_s_part[NB * NC1 * ND];     // 1 MB
__device__ __align__(16) float g_s[NB * ND];                // 64 KB
__device__ float g_pm[NB * NPART];
__device__ float g_pl[NB * NPART];
__device__ __align__(16) float g_pacc[(size_t)NB * NPART * ND];  // 4 MB

// ---------------------------------------------------------------------------
// Pass 1a: partial column sums over T-chunks. Block = 128 threads, one float4
// per thread covers all 512 d's. Grid (NB, NC1) = 512 blocks.
// ---------------------------------------------------------------------------
__global__ void __launch_bounds__(128) k_sum_partial(const float* __restrict__ x) {
    const int b = blockIdx.x, c = blockIdx.y, tid = threadIdx.x;
    const float4* xp =
        (const float4*)(x + ((size_t)b * NT + (size_t)c * ROWS1) * ND);

    float4 a0 = {0.f, 0.f, 0.f, 0.f}, a1 = a0, a2 = a0, a3 = a0;
    #pragma unroll 2
    for (int r = 0; r < ROWS1; r += 4) {
        float4 v0 = xp[(size_t)(r + 0) * (ND / 4) + tid];
        float4 v1 = xp[(size_t)(r + 1) * (ND / 4) + tid];
        float4 v2 = xp[(size_t)(r + 2) * (ND / 4) + tid];
        float4 v3 = xp[(size_t)(r + 3) * (ND / 4) + tid];
        a0.x += v0.x; a0.y += v0.y; a0.z += v0.z; a0.w += v0.w;
        a1.x += v1.x; a1.y += v1.y; a1.z += v1.z; a1.w += v1.w;
        a2.x += v2.x; a2.y += v2.y; a2.z += v2.z; a2.w += v2.w;
        a3.x += v3.x; a3.y += v3.y; a3.z += v3.z; a3.w += v3.w;
    }
    float4 a;
    a.x = (a0.x + a1.x) + (a2.x + a3.x);
    a.y = (a0.y + a1.y) + (a2.y + a3.y);
    a.z = (a0.z + a1.z) + (a2.z + a3.z);
    a.w = (a0.w + a1.w) + (a2.w + a3.w);
    ((float4*)(g_s_part + ((size_t)b * NC1 + c) * ND))[tid] = a;
}

// ---------------------------------------------------------------------------
// Pass 1b: fold the NC1 partials in a FIXED order (deterministic fp32).
// ---------------------------------------------------------------------------
__global__ void __launch_bounds__(256) k_sum_final() {
    const int idx = blockIdx.x * blockDim.x + threadIdx.x;  // 0..NB*ND-1
    const int b = idx / ND, d = idx % ND;
    float s = 0.f;
    #pragma unroll
    for (int c = 0; c < NC1; ++c)
        s += g_s_part[((size_t)b * NC1 + c) * ND + d];
    g_s[idx] = s;
}

// ---------------------------------------------------------------------------
// Pass 2: fused w + online-softmax + weighted pooling, ONE read of x.
// One warp owns RPW rows; per row: 4×LDG.128 per lane (full 512-f row per
// warp), w = sum_d x_d*(s_d - x_d) -> single 5-shuffle reduction, then
// rescale-and-accumulate the row into a register-resident acc[16/lane].
// Batches processed in REVERSE order to hit pass-1's still-warm L2 lines.
// ---------------------------------------------------------------------------
__global__ void __launch_bounds__(256) k_pool(const float* __restrict__ x) {
    const int b = NB - 1 - blockIdx.x;
    const int c = blockIdx.y;
    const int w = threadIdx.x >> 5, lane = threadIdx.x & 31;

    const float4* sb = (const float4*)(g_s + (size_t)b * ND);
    const float4 s0 = sb[lane], s1 = sb[32 + lane], s2 = sb[64 + lane],
                 s3 = sb[96 + lane];

    float m = -FLT_MAX, l = 0.f;
    float4 a0 = {0.f, 0.f, 0.f, 0.f}, a1 = a0, a2 = a0, a3 = a0;

    const float4* xb = (const float4*)(x + (size_t)b * NT * ND);
    const int tbase = c * (NT / NC2) + w;

    for (int j = 0; j < RPW; ++j) {
        const int t = tbase + j * NW2;
        const float4* row = xb + (size_t)t * (ND / 4);
        const float4 v0 = row[lane];
        const float4 v1 = row[32 + lane];
        const float4 v2 = row[64 + lane];
        const float4 v3 = row[96 + lane];

        // per-lane partial of w = sum x*(s - x)
        float r = 0.f;
        r = fmaf(v0.x, s0.x - v0.x, r); r = fmaf(v0.y, s0.y - v0.y, r);
        r = fmaf(v0.z, s0.z - v0.z, r); r = fmaf(v0.w, s0.w - v0.w, r);
        r = fmaf(v1.x, s1.x - v1.x, r); r = fmaf(v1.y, s1.y - v1.y, r);
        r = fmaf(v1.z, s1.z - v1.z, r); r = fmaf(v1.w, s1.w - v1.w, r);
        r = fmaf(v2.x, s2.x - v2.x, r); r = fmaf(v2.y, s2.y - v2.y, r);
        r = fmaf(v2.z, s2.z - v2.z, r); r = fmaf(v2.w, s2.w - v2.w, r);
        r = fmaf(v3.x, s3.x - v3.x, r); r = fmaf(v3.y, s3.y - v3.y, r);
        r = fmaf(v3.z, s3.z - v3.z, r); r = fmaf(v3.w, s3.w - v3.w, r);

        #pragma unroll
        for (int o = 16; o; o >>= 1)
            r += __shfl_xor_sync(0xffffffffu, r, o);

        // online softmax update
        const float mn = fmaxf(m, r);
        const float sc = __expf(m - mn);   // 0 on first iter (m = -FLT_MAX)
        const float p  = __expf(r - mn);
        l = l * sc + p;
        a0.x = fmaf(a0.x, sc, p * v0.x); a0.y = fmaf(a0.y, sc, p * v0.y);
        a0.z = fmaf(a0.z, sc, p * v0.z); a0.w = fmaf(a0.w, sc, p * v0.w);
        a1.x = fmaf(a1.x, sc, p * v1.x); a1.y = fmaf(a1.y, sc, p * v1.y);
        a1.z = fmaf(a1.z, sc, p * v1.z); a1.w = fmaf(a1.w, sc, p * v1.w);
        a2.x = fmaf(a2.x, sc, p * v2.x); a2.y = fmaf(a2.y, sc, p * v2.y);
        a2.z = fmaf(a2.z, sc, p * v2.z); a2.w = fmaf(a2.w, sc, p * v2.w);
        a3.x = fmaf(a3.x, sc, p * v3.x); a3.y = fmaf(a3.y, sc, p * v3.y);
        a3.z = fmaf(a3.z, sc, p * v3.z); a3.w = fmaf(a3.w, sc, p * v3.w);
        m = mn;
    }

    const int pi = (b * NC2 + c) * NW2 + w;
    if (lane == 0) { g_pm[pi] = m; g_pl[pi] = l; }
    float4* pa = (float4*)(g_pacc + (size_t)pi * ND);
    pa[lane] = a0; pa[32 + lane] = a1; pa[64 + lane] = a2; pa[96 + lane] = a3;
}

// ---------------------------------------------------------------------------
// Pass 3: merge 64 split-softmax partials per batch. All threads walk the
// partials in the same fixed order (broadcast loads, deterministic).
// ---------------------------------------------------------------------------
__global__ void __launch_bounds__(128) k_combine(float* __restrict__ out) {
    const int b = blockIdx.x, tid = threadIdx.x;  // tid*4 covers d
    const float* pm = g_pm + b * NPART;
    const float* pl = g_pl + b * NPART;

    float M = -FLT_MAX;
    #pragma unroll
    for (int p = 0; p < NPART; ++p) M = fmaxf(M, pm[p]);

    float L = 0.f;
    float4 o = {0.f, 0.f, 0.f, 0.f};
    #pragma unroll 4
    for (int p = 0; p < NPART; ++p) {
        const float e = __expf(pm[p] - M);
        L = fmaf(pl[p], e, L);
        const float4 a =
            ((const float4*)(g_pacc + (size_t)(b * NPART + p) * ND))[tid];
        o.x = fmaf(e, a.x, o.x); o.y = fmaf(e, a.y, o.y);
        o.z = fmaf(e, a.z, o.z); o.w = fmaf(e, a.w, o.w);
    }
    const float inv = 1.f / L;
    o.x *= inv; o.y *= inv; o.z *= inv; o.w *= inv;
    ((float4*)(out + (size_t)b * ND))[tid] = o;
}

// ---------------------------------------------------------------------------
extern "C" void kernel_launch(void* const* d_in, const int* in_sizes, int n_in,
                              void* d_out, int out_size) {
    (void)in_sizes; (void)n_in; (void)out_size;
    const float* x = (const float*)d_in[0];
    float* out = (float*)d_out;

    k_sum_partial<<<dim3(NB, NC1), 128>>>(x);
    k_sum_final<<<(NB * ND) / 256, 256>>>();
    k_pool<<<dim3(NB, NC2), 256>>>(x);
    k_combine<<<NB, 128>>>(out);
}

// round 2
// speedup vs baseline: 1.1312x; 1.1312x over previous
#include <cuda_runtime.h>
#include <float.h>

// Problem shape (fixed by the reference)
#define NB 32
#define NT 2048
#define ND 512

// Pass-1 chunking
#define NC1 32
#define ROWS1 (NT / NC1)           // 64 rows per block

// Pass-2 chunking: grid (NB, NC2), 8 warps/block; warps merge in-block
#define NC2 8
#define NW2 8
#define RPW ((NT / NC2) / NW2)     // 32 rows per warp
#define NPART NC2                  // 8 block-partials per batch

// Scratch (no cudaMalloc allowed)
__device__ __align__(16) float g_s_part[NB * NC1 * ND];          // 2 MB
__device__ __align__(16) float g_s[NB * ND];                     // 64 KB
__device__ float g_pm[NB * NPART];
__device__ float g_pl[NB * NPART];
__device__ __align__(16) float g_pacc[(size_t)NB * NPART * ND];  // 512 KB

// ---------------------------------------------------------------------------
// Pass 1a: partial column sums over T-chunks. 128 threads = one float4 lane
// across the 512-wide row. Grid (NB, NC1) = 1024 blocks.
// ---------------------------------------------------------------------------
__global__ void __launch_bounds__(128) k_sum_partial(const float* __restrict__ x) {
    const int b = blockIdx.x, c = blockIdx.y, tid = threadIdx.x;
    const float4* xp =
        (const float4*)(x + ((size_t)b * NT + (size_t)c * ROWS1) * ND);

    float4 a0 = {0.f, 0.f, 0.f, 0.f}, a1 = a0, a2 = a0, a3 = a0;
    #pragma unroll 2
    for (int r = 0; r < ROWS1; r += 4) {
        float4 v0 = xp[(size_t)(r + 0) * (ND / 4) + tid];
        float4 v1 = xp[(size_t)(r + 1) * (ND / 4) + tid];
        float4 v2 = xp[(size_t)(r + 2) * (ND / 4) + tid];
        float4 v3 = xp[(size_t)(r + 3) * (ND / 4) + tid];
        a0.x += v0.x; a0.y += v0.y; a0.z += v0.z; a0.w += v0.w;
        a1.x += v1.x; a1.y += v1.y; a1.z += v1.z; a1.w += v1.w;
        a2.x += v2.x; a2.y += v2.y; a2.z += v2.z; a2.w += v2.w;
        a3.x += v3.x; a3.y += v3.y; a3.z += v3.z; a3.w += v3.w;
    }
    float4 a;
    a.x = (a0.x + a1.x) + (a2.x + a3.x);
    a.y = (a0.y + a1.y) + (a2.y + a3.y);
    a.z = (a0.z + a1.z) + (a2.z + a3.z);
    a.w = (a0.w + a1.w) + (a2.w + a3.w);
    ((float4*)(g_s_part + ((size_t)b * NC1 + c) * ND))[tid] = a;
}

// ---------------------------------------------------------------------------
// Pass 1b: fold NC1 partials in FIXED order (deterministic). Vectorized.
// ---------------------------------------------------------------------------
__global__ void __launch_bounds__(256) k_sum_final() {
    const int idx = blockIdx.x * blockDim.x + threadIdx.x;  // 0..NB*ND/4-1
    const int b = idx / (ND / 4), q = idx % (ND / 4);
    float4 s = {0.f, 0.f, 0.f, 0.f};
    #pragma unroll
    for (int c = 0; c < NC1; ++c) {
        const float4 v =
            ((const float4*)(g_s_part + ((size_t)b * NC1 + c) * ND))[q];
        s.x += v.x; s.y += v.y; s.z += v.z; s.w += v.w;
    }
    ((float4*)g_s)[idx] = s;
}

// ---------------------------------------------------------------------------
// Pass 2: fused w + online-softmax + pooling, ONE read of x.
// Warp-level split softmax, then in-block merge of 8 warps via smem -> one
// partial per block. Fully reversed traversal (batch+chunk) for L2 reuse of
// pass-1's tail. Warp-uniform branch: rescale only when max improves.
// ---------------------------------------------------------------------------
__global__ void __launch_bounds__(256) k_pool(const float* __restrict__ x) {
    const int b = NB - 1 - blockIdx.x;
    const int c = NC2 - 1 - blockIdx.y;
    const int w = threadIdx.x >> 5, lane = threadIdx.x & 31;

    __shared__ float sm_m[NW2], sm_l[NW2];
    __shared__ __align__(16) float sm_acc[NW2][ND];   // 16 KB

    const float4* sb = (const float4*)(g_s + (size_t)b * ND);
    const float4 s0 = sb[lane], s1 = sb[32 + lane], s2 = sb[64 + lane],
                 s3 = sb[96 + lane];

    float m = -FLT_MAX, l = 0.f;
    float4 a0 = {0.f, 0.f, 0.f, 0.f}, a1 = a0, a2 = a0, a3 = a0;

    const float4* xb = (const float4*)(x + (size_t)b * NT * ND);
    const int tbase = c * (NT / NC2) + w;

    for (int j = RPW - 1; j >= 0; --j) {
        const int t = tbase + j * NW2;
        const float4* row = xb + (size_t)t * (ND / 4);
        const float4 v0 = row[lane];
        const float4 v1 = row[32 + lane];
        const float4 v2 = row[64 + lane];
        const float4 v3 = row[96 + lane];

        // per-lane partial of w = sum x*(s - x)
        float r = 0.f;
        r = fmaf(v0.x, s0.x - v0.x, r); r = fmaf(v0.y, s0.y - v0.y, r);
        r = fmaf(v0.z, s0.z - v0.z, r); r = fmaf(v0.w, s0.w - v0.w, r);
        r = fmaf(v1.x, s1.x - v1.x, r); r = fmaf(v1.y, s1.y - v1.y, r);
        r = fmaf(v1.z, s1.z - v1.z, r); r = fmaf(v1.w, s1.w - v1.w, r);
        r = fmaf(v2.x, s2.x - v2.x, r); r = fmaf(v2.y, s2.y - v2.y, r);
        r = fmaf(v2.z, s2.z - v2.z, r); r = fmaf(v2.w, s2.w - v2.w, r);
        r = fmaf(v3.x, s3.x - v3.x, r); r = fmaf(v3.y, s3.y - v3.y, r);
        r = fmaf(v3.z, s3.z - v3.z, r); r = fmaf(v3.w, s3.w - v3.w, r);

        #pragma unroll
        for (int o = 16; o; o >>= 1)
            r += __shfl_xor_sync(0xffffffffu, r, o);

        if (r > m) {                      // warp-uniform; p = exp(r-r) = 1
            const float sc = __expf(m - r);
            l = fmaf(l, sc, 1.f);
            a0.x = fmaf(a0.x, sc, v0.x); a0.y = fmaf(a0.y, sc, v0.y);
            a0.z = fmaf(a0.z, sc, v0.z); a0.w = fmaf(a0.w, sc, v0.w);
            a1.x = fmaf(a1.x, sc, v1.x); a1.y = fmaf(a1.y, sc, v1.y);
            a1.z = fmaf(a1.z, sc, v1.z); a1.w = fmaf(a1.w, sc, v1.w);
            a2.x = fmaf(a2.x, sc, v2.x); a2.y = fmaf(a2.y, sc, v2.y);
            a2.z = fmaf(a2.z, sc, v2.z); a2.w = fmaf(a2.w, sc, v2.w);
            a3.x = fmaf(a3.x, sc, v3.x); a3.y = fmaf(a3.y, sc, v3.y);
            a3.z = fmaf(a3.z, sc, v3.z); a3.w = fmaf(a3.w, sc, v3.w);
            m = r;
        } else {                          // common path: no rescale
            const float p = __expf(r - m);
            l += p;
            a0.x = fmaf(p, v0.x, a0.x); a0.y = fmaf(p, v0.y, a0.y);
            a0.z = fmaf(p, v0.z, a0.z); a0.w = fmaf(p, v0.w, a0.w);
            a1.x = fmaf(p, v1.x, a1.x); a1.y = fmaf(p, v1.y, a1.y);
            a1.z = fmaf(p, v1.z, a1.z); a1.w = fmaf(p, v1.w, a1.w);
            a2.x = fmaf(p, v2.x, a2.x); a2.y = fmaf(p, v2.y, a2.y);
            a2.z = fmaf(p, v2.z, a2.z); a2.w = fmaf(p, v2.w, a2.w);
            a3.x = fmaf(p, v3.x, a3.x); a3.y = fmaf(p, v3.y, a3.y);
            a3.z = fmaf(p, v3.z, a3.z); a3.w = fmaf(p, v3.w, a3.w);
        }
    }

    // stash warp partials in smem
    if (lane == 0) { sm_m[w] = m; sm_l[w] = l; }
    float4* sa = (float4*)sm_acc[w];
    sa[lane] = a0; sa[32 + lane] = a1; sa[64 + lane] = a2; sa[96 + lane] = a3;
    __syncthreads();

    // in-block merge: first 128 threads, one float4 of d each, FIXED order
    const int tid = threadIdx.x;
    if (tid < ND / 4) {
        float M = -FLT_MAX;
        #pragma unroll
        for (int p = 0; p < NW2; ++p) M = fmaxf(M, sm_m[p]);
        float L = 0.f;
        float4 o = {0.f, 0.f, 0.f, 0.f};
        #pragma unroll
        for (int p = 0; p < NW2; ++p) {
            const float e = __expf(sm_m[p] - M);
            L = fmaf(sm_l[p], e, L);
            const float4 a = ((const float4*)sm_acc[p])[tid];
            o.x = fmaf(e, a.x, o.x); o.y = fmaf(e, a.y, o.y);
            o.z = fmaf(e, a.z, o.z); o.w = fmaf(e, a.w, o.w);
        }
        const int pi = b * NPART + c;
        if (tid == 0) { g_pm[pi] = M; g_pl[pi] = L; }
        ((float4*)(g_pacc + (size_t)pi * ND))[tid] = o;
    }
}

// ---------------------------------------------------------------------------
// Pass 3: merge 8 block-partials per batch (fully unrolled -> all loads in
// flight). Fixed order = deterministic.
// ---------------------------------------------------------------------------
__global__ void __launch_bounds__(128) k_combine(float* __restrict__ out) {
    const int b = blockIdx.x, tid = threadIdx.x;
    const float* pm = g_pm + b * NPART;
    const float* pl = g_pl + b * NPART;

    float M = -FLT_MAX;
    #pragma unroll
    for (int p = 0; p < NPART; ++p) M = fmaxf(M, pm[p]);

    float L = 0.f;
    float4 o = {0.f, 0.f, 0.f, 0.f};
    #pragma unroll
    for (int p = 0; p < NPART; ++p) {
        const float e = __expf(pm[p] - M);
        L = fmaf(pl[p], e, L);
        const float4 a =
            ((const float4*)(g_pacc + (size_t)(b * NPART + p) * ND))[tid];
        o.x = fmaf(e, a.x, o.x); o.y = fmaf(e, a.y, o.y);
        o.z = fmaf(e, a.z, o.z); o.w = fmaf(e, a.w, o.w);
    }
    const float inv = 1.f / L;
    o.x *= inv; o.y *= inv; o.z *= inv; o.w *= inv;
    ((float4*)(out + (size_t)b * ND))[tid] = o;
}

// ---------------------------------------------------------------------------
extern "C" void kernel_launch(void* const* d_in, const int* in_sizes, int n_in,
                              void* d_out, int out_size) {
    (void)in_sizes; (void)n_in; (void)out_size;
    const float* x = (const float*)d_in[0];
    float* out = (float*)d_out;

    k_sum_partial<<<dim3(NB, NC1), 128>>>(x);
    k_sum_final<<<(NB * ND / 4) / 256, 256>>>();
    k_pool<<<dim3(NB, NC2), 256>>>(x);
    k_combine<<<NB, 128>>>(out);
}

// round 3
// speedup vs baseline: 1.8843x; 1.6658x over previous
#include <cuda_runtime.h>
#include <float.h>

// Problem shape (fixed by the reference)
#define NB 32
#define NT 2048
#define ND 512

#define NC 8                 // chunks (blocks) per batch
#define NW 8                 // warps per block
#define ROWS (NT / NC)       // 256 rows per block
#define RPW (ROWS / NW)      // 32 rows per warp

// Scratch (no cudaMalloc allowed)
__device__ __align__(16) float g_s_part[NB * NC * ND];           // 512 KB
__device__ float g_pm[NB * NC];
__device__ float g_pl[NB * NC];
__device__ __align__(16) float g_pacc[(size_t)NB * NC * ND];     // 512 KB
__device__ int g_cnt_s[NB];   // zero-init; reset by last block each launch
__device__ int g_cnt_p[NB];

__device__ __forceinline__ void f4add(float4& a, const float4 b) {
    a.x += b.x; a.y += b.y; a.z += b.z; a.w += b.w;
}

// ---------------------------------------------------------------------------
// Fully fused: per-block column sum -> per-batch inter-block barrier ->
// s fold -> online-softmax pooling (reverse row order for L2 reuse) ->
// in-block merge -> last block per batch combines and writes output.
// All fold orders fixed -> bit-deterministic.
// ---------------------------------------------------------------------------
__global__ void __launch_bounds__(256, 2)
k_fused(const float* __restrict__ x, float* __restrict__ out) {
    const int b = blockIdx.x, c = blockIdx.y;
    const int tid = threadIdx.x, w = tid >> 5, lane = tid & 31;

    __shared__ float sm_m[NW], sm_l[NW];
    __shared__ int sm_last;
    __shared__ __align__(16) float sm_acc[NW][ND];   // 16 KB, reused twice

    const float4* xb = (const float4*)(x + (size_t)b * NT * ND);
    const int tbase = c * ROWS + w;                  // rows: tbase + j*NW

    // ---- Phase 1: column-sum of this block's 256 rows (ascending j) ----
    float4 q0 = {0.f, 0.f, 0.f, 0.f}, q1 = q0, q2 = q0, q3 = q0;
    #pragma unroll 2
    for (int j = 0; j < RPW; ++j) {
        const float4* row = xb + (size_t)(tbase + j * NW) * (ND / 4);
        f4add(q0, row[lane]);      f4add(q1, row[32 + lane]);
        f4add(q2, row[64 + lane]); f4add(q3, row[96 + lane]);
    }
    {
        float4* sa = (float4*)sm_acc[w];
        sa[lane] = q0; sa[32 + lane] = q1; sa[64 + lane] = q2; sa[96 + lane] = q3;
    }
    __syncthreads();
    if (tid < ND / 4) {
        float4 s = {0.f, 0.f, 0.f, 0.f};
        #pragma unroll
        for (int p = 0; p < NW; ++p) f4add(s, ((const float4*)sm_acc[p])[tid]);
        ((float4*)(g_s_part + (size_t)(b * NC + c) * ND))[tid] = s;
    }
    __threadfence();
    __syncthreads();

    // ---- Per-batch inter-block barrier (all 256 blocks co-resident) ----
    if (tid == 0) {
        atomicAdd(&g_cnt_s[b], 1);
        while (atomicAdd(&g_cnt_s[b], 0) < NC) __nanosleep(128);
    }
    __syncthreads();
    __threadfence();

    // ---- Fold the 8 partials (fixed order) -> s in registers ----
    const float4* sp = (const float4*)(g_s_part + (size_t)b * NC * ND);
    float4 s0 = {0.f, 0.f, 0.f, 0.f}, s1 = s0, s2 = s0, s3 = s0;
    #pragma unroll
    for (int p = 0; p < NC; ++p) {
        const float4* pp = sp + p * (ND / 4);
        f4add(s0, pp[lane]);      f4add(s1, pp[32 + lane]);
        f4add(s2, pp[64 + lane]); f4add(s3, pp[96 + lane]);
    }

    // ---- Phase 2: online-softmax pooling, reverse row order (L2-hot) ----
    float m = -FLT_MAX, l = 0.f;
    float4 a0 = {0.f, 0.f, 0.f, 0.f}, a1 = a0, a2 = a0, a3 = a0;

    for (int j = RPW - 1; j >= 0; --j) {
        const float4* row = xb + (size_t)(tbase + j * NW) * (ND / 4);
        const float4 v0 = row[lane];
        const float4 v1 = row[32 + lane];
        const float4 v2 = row[64 + lane];
        const float4 v3 = row[96 + lane];

        // per-lane partial of w = sum_d x*(s - x)
        float r = 0.f;
        r = fmaf(v0.x, s0.x - v0.x, r); r = fmaf(v0.y, s0.y - v0.y, r);
        r = fmaf(v0.z, s0.z - v0.z, r); r = fmaf(v0.w, s0.w - v0.w, r);
        r = fmaf(v1.x, s1.x - v1.x, r); r = fmaf(v1.y, s1.y - v1.y, r);
        r = fmaf(v1.z, s1.z - v1.z, r); r = fmaf(v1.w, s1.w - v1.w, r);
        r = fmaf(v2.x, s2.x - v2.x, r); r = fmaf(v2.y, s2.y - v2.y, r);
        r = fmaf(v2.z, s2.z - v2.z, r); r = fmaf(v2.w, s2.w - v2.w, r);
        r = fmaf(v3.x, s3.x - v3.x, r); r = fmaf(v3.y, s3.y - v3.y, r);
        r = fmaf(v3.z, s3.z - v3.z, r); r = fmaf(v3.w, s3.w - v3.w, r);

        #pragma unroll
        for (int o = 16; o; o >>= 1)
            r += __shfl_xor_sync(0xffffffffu, r, o);

        if (r > m) {                       // warp-uniform; p = 1
            const float sc = __expf(m - r);
            l = fmaf(l, sc, 1.f);
            a0.x = fmaf(a0.x, sc, v0.x); a0.y = fmaf(a0.y, sc, v0.y);
            a0.z = fmaf(a0.z, sc, v0.z); a0.w = fmaf(a0.w, sc, v0.w);
            a1.x = fmaf(a1.x, sc, v1.x); a1.y = fmaf(a1.y, sc, v1.y);
            a1.z = fmaf(a1.z, sc, v1.z); a1.w = fmaf(a1.w, sc, v1.w);
            a2.x = fmaf(a2.x, sc, v2.x); a2.y = fmaf(a2.y, sc, v2.y);
            a2.z = fmaf(a2.z, sc, v2.z); a2.w = fmaf(a2.w, sc, v2.w);
            a3.x = fmaf(a3.x, sc, v3.x); a3.y = fmaf(a3.y, sc, v3.y);
            a3.z = fmaf(a3.z, sc, v3.z); a3.w = fmaf(a3.w, sc, v3.w);
            m = r;
        } else {                           // common path: no rescale
            const float p = __expf(r - m);
            l += p;
            a0.x = fmaf(p, v0.x, a0.x); a0.y = fmaf(p, v0.y, a0.y);
            a0.z = fmaf(p, v0.z, a0.z); a0.w = fmaf(p, v0.w, a0.w);
            a1.x = fmaf(p, v1.x, a1.x); a1.y = fmaf(p, v1.y, a1.y);
            a1.z = fmaf(p, v1.z, a1.z); a1.w = fmaf(p, v1.w, a1.w);
            a2.x = fmaf(p, v2.x, a2.x); a2.y = fmaf(p, v2.y, a2.y);
            a2.z = fmaf(p, v2.z, a2.z); a2.w = fmaf(p, v2.w, a2.w);
            a3.x = fmaf(p, v3.x, a3.x); a3.y = fmaf(p, v3.y, a3.y);
            a3.z = fmaf(p, v3.z, a3.z); a3.w = fmaf(p, v3.w, a3.w);
        }
    }

    // ---- In-block merge of 8 warp partials (fixed order) ----
    __syncthreads();                       // sm_acc reuse guard
    if (lane == 0) { sm_m[w] = m; sm_l[w] = l; }
    {
        float4* sa = (float4*)sm_acc[w];
        sa[lane] = a0; sa[32 + lane] = a1; sa[64 + lane] = a2; sa[96 + lane] = a3;
    }
    __syncthreads();
    if (tid < ND / 4) {
        float M = -FLT_MAX;
        #pragma unroll
        for (int p = 0; p < NW; ++p) M = fmaxf(M, sm_m[p]);
        float L = 0.f;
        float4 o = {0.f, 0.f, 0.f, 0.f};
        #pragma unroll
        for (int p = 0; p < NW; ++p) {
            const float e = __expf(sm_m[p] - M);
            L = fmaf(sm_l[p], e, L);
            const float4 a = ((const float4*)sm_acc[p])[tid];
            o.x = fmaf(e, a.x, o.x); o.y = fmaf(e, a.y, o.y);
            o.z = fmaf(e, a.z, o.z); o.w = fmaf(e, a.w, o.w);
        }
        const int pi = b * NC + c;
        if (tid == 0) { g_pm[pi] = M; g_pl[pi] = L; }
        ((float4*)(g_pacc + (size_t)pi * ND))[tid] = o;
    }
    __threadfence();
    __syncthreads();

    // ---- Last block per batch combines and writes output ----
    if (tid == 0) {
        const int old = atomicAdd(&g_cnt_p[b], 1);
        sm_last = (old == NC - 1);
    }
    __syncthreads();
    if (sm_last) {
        __threadfence();
        if (tid < ND / 4) {
            const float* pm = g_pm + b * NC;
            const float* pl = g_pl + b * NC;
            float M = -FLT_MAX;
            #pragma unroll
            for (int p = 0; p < NC; ++p) M = fmaxf(M, pm[p]);
            float L = 0.f;
            float4 o = {0.f, 0.f, 0.f, 0.f};
            #pragma unroll
            for (int p = 0; p < NC; ++p) {
                const float e = __expf(pm[p] - M);
                L = fmaf(pl[p], e, L);
                const float4 a =
                    ((const float4*)(g_pacc + (size_t)(b * NC + p) * ND))[tid];
                o.x = fmaf(e, a.x, o.x); o.y = fmaf(e, a.y, o.y);
                o.z = fmaf(e, a.z, o.z); o.w = fmaf(e, a.w, o.w);
            }
            const float inv = 1.f / L;
            o.x *= inv; o.y *= inv; o.z *= inv; o.w *= inv;
            ((float4*)(out + (size_t)b * ND))[tid] = o;
        }
        // reset counters for the next graph replay (all 8 blocks of this
        // batch have passed both barriers by construction)
        if (tid == 0) {
            atomicExch(&g_cnt_s[b], 0);
            atomicExch(&g_cnt_p[b], 0);
        }
    }
}

// ---------------------------------------------------------------------------
extern "C" void kernel_launch(void* const* d_in, const int* in_sizes, int n_in,
                              void* d_out, int out_size) {
    (void)in_sizes; (void)n_in; (void)out_size;
    const float* x = (const float*)d_in[0];
    float* out = (float*)d_out;

    k_fused<<<dim3(NB, NC), 256>>>(x, out);
}